// round 6
// baseline (speedup 1.0000x reference)
#include <cuda_runtime.h>
#include <cuda_bf16.h>

#define BM 128
#define BN 128
#define BK 16
#define TM 8
#define TN 8
#define THREADS 256

#define M_DIM 16384
#define N_DIM 12288
#define K_DIM 4096
#define SEG   4096          // output segment width (E)

#define NT_TILES (N_DIM / BN)   // 96
#define MT_TILES (M_DIM / BM)   // 128
#define BAND 48                 // N-tiles per L2 band (48*128*4096*4 = 96MB of B)

__global__ __launch_bounds__(THREADS, 2)
void qkv_gemm_kernel(const float* __restrict__ A,   // [M, K] hidden
                     const float* __restrict__ B,   // [N, K] qkv_proj
                     float* __restrict__ Cout)      // 3 segments of [M, SEG]
{
    // ---- band-swizzled tile coordinates (keep a 96MB B-band resident in L2) ----
    int tile   = blockIdx.x;
    int band   = tile / (BAND * MT_TILES);
    int within = tile - band * (BAND * MT_TILES);
    int nt     = band * BAND + (within % BAND);
    int mt     = within / BAND;

    const int m0 = mt * BM;
    const int n0 = nt * BN;

    // double-buffered k-major tiles (transposed: [k][m]/[k][n]) with padding
    __shared__ float As[2][BK][BM + 4];
    __shared__ float Bs[2][BK][BN + 4];

    const int tid = threadIdx.x;

    // global-load mapping: 128 rows x 4 float4 per tile; each thread does rows lr and lr+64
    const int lr = tid >> 2;            // 0..63
    const int lc = (tid & 3) << 2;      // k-offset within tile: 0,4,8,12

    const float* Aptr = A + (size_t)(m0 + lr) * K_DIM + lc;
    const float* Bptr = B + (size_t)(n0 + lr) * K_DIM + lc;

    // compute mapping: 16x16 threads, each owns an 8x8 micro-tile
    const int tx = tid & 15;            // -> n
    const int ty = tid >> 4;            // -> m
    const int mrow = ty * TM;
    const int ncol = tx * TN;

    float acc[TM][TN];
#pragma unroll
    for (int i = 0; i < TM; i++)
#pragma unroll
        for (int j = 0; j < TN; j++) acc[i][j] = 0.0f;

    const int KT = K_DIM / BK;          // 256 k-tiles

    // ---- prologue: load k-tile 0 into buffer 0 ----
    {
        float4 a0 = *(const float4*)(Aptr);
        float4 a1 = *(const float4*)(Aptr + (size_t)64 * K_DIM);
        float4 b0 = *(const float4*)(Bptr);
        float4 b1 = *(const float4*)(Bptr + (size_t)64 * K_DIM);

        As[0][lc + 0][lr] = a0.x; As[0][lc + 1][lr] = a0.y; As[0][lc + 2][lr] = a0.z; As[0][lc + 3][lr] = a0.w;
        As[0][lc + 0][lr + 64] = a1.x; As[0][lc + 1][lr + 64] = a1.y; As[0][lc + 2][lr + 64] = a1.z; As[0][lc + 3][lr + 64] = a1.w;
        Bs[0][lc + 0][lr] = b0.x; Bs[0][lc + 1][lr] = b0.y; Bs[0][lc + 2][lr] = b0.z; Bs[0][lc + 3][lr] = b0.w;
        Bs[0][lc + 0][lr + 64] = b1.x; Bs[0][lc + 1][lr + 64] = b1.y; Bs[0][lc + 2][lr + 64] = b1.z; Bs[0][lc + 3][lr + 64] = b1.w;
    }
    __syncthreads();

    int buf = 0;
    // steady state: KT-1 iterations with prefetch; last tile peeled (no guard in body)
    for (int kt = 0; kt < KT - 1; kt++) {
        // 1) issue prefetch LDGs for the next k-tile
        const float* ap = Aptr + (size_t)(kt + 1) * BK;
        const float* bp = Bptr + (size_t)(kt + 1) * BK;
        float4 na0 = *(const float4*)(ap);
        float4 na1 = *(const float4*)(ap + (size_t)64 * K_DIM);
        float4 nb0 = *(const float4*)(bp);
        float4 nb1 = *(const float4*)(bp + (size_t)64 * K_DIM);

        // 2) compute on the current buffer (~1024 FFMA per thread hides the LDGs)
#pragma unroll
        for (int kk = 0; kk < BK; kk++) {
            float4 av0 = *(const float4*)(&As[buf][kk][mrow]);
            float4 av1 = *(const float4*)(&As[buf][kk][mrow + 4]);
            float4 bv0 = *(const float4*)(&Bs[buf][kk][ncol]);
            float4 bv1 = *(const float4*)(&Bs[buf][kk][ncol + 4]);
            float a[TM] = {av0.x, av0.y, av0.z, av0.w, av1.x, av1.y, av1.z, av1.w};
            float b[TN] = {bv0.x, bv0.y, bv0.z, bv0.w, bv1.x, bv1.y, bv1.z, bv1.w};
#pragma unroll
            for (int i = 0; i < TM; i++)
#pragma unroll
                for (int j = 0; j < TN; j++)
                    acc[i][j] = fmaf(a[i], b[j], acc[i][j]);
        }

        // 3) stage landed registers into the other buffer (race-free: buf^1 was
        //    last read before the barrier that ended the previous iteration)
        const int nb = buf ^ 1;
        As[nb][lc + 0][lr] = na0.x; As[nb][lc + 1][lr] = na0.y; As[nb][lc + 2][lr] = na0.z; As[nb][lc + 3][lr] = na0.w;
        As[nb][lc + 0][lr + 64] = na1.x; As[nb][lc + 1][lr + 64] = na1.y; As[nb][lc + 2][lr + 64] = na1.z; As[nb][lc + 3][lr + 64] = na1.w;
        Bs[nb][lc + 0][lr] = nb0.x; Bs[nb][lc + 1][lr] = nb0.y; Bs[nb][lc + 2][lr] = nb0.z; Bs[nb][lc + 3][lr] = nb0.w;
        Bs[nb][lc + 0][lr + 64] = nb1.x; Bs[nb][lc + 1][lr + 64] = nb1.y; Bs[nb][lc + 2][lr + 64] = nb1.z; Bs[nb][lc + 3][lr + 64] = nb1.w;

        // 4) single barrier per k-tile
        __syncthreads();
        buf ^= 1;
    }

    // peeled last k-tile: compute only
#pragma unroll
    for (int kk = 0; kk < BK; kk++) {
        float4 av0 = *(const float4*)(&As[buf][kk][mrow]);
        float4 av1 = *(const float4*)(&As[buf][kk][mrow + 4]);
        float4 bv0 = *(const float4*)(&Bs[buf][kk][ncol]);
        float4 bv1 = *(const float4*)(&Bs[buf][kk][ncol + 4]);
        float a[TM] = {av0.x, av0.y, av0.z, av0.w, av1.x, av1.y, av1.z, av1.w};
        float b[TN] = {bv0.x, bv0.y, bv0.z, bv0.w, bv1.x, bv1.y, bv1.z, bv1.w};
#pragma unroll
        for (int i = 0; i < TM; i++)
#pragma unroll
            for (int j = 0; j < TN; j++)
                acc[i][j] = fmaf(a[i], b[j], acc[i][j]);
    }

    // ---- epilogue: map GEMM column n -> (segment, col) and stream out ----
    const int seg = n0 >> 12;                 // BN=128 divides 4096, so whole tile in one segment
    const int c0  = (n0 & (SEG - 1)) + ncol;
    float* outseg = Cout + (size_t)seg * ((size_t)M_DIM * SEG);

#pragma unroll
    for (int i = 0; i < TM; i++) {
        const int m = m0 + mrow + i;
        float* row = outseg + (size_t)m * SEG + c0;
        float4 v0 = make_float4(acc[i][0], acc[i][1], acc[i][2], acc[i][3]);
        float4 v1 = make_float4(acc[i][4], acc[i][5], acc[i][6], acc[i][7]);
        __stcs((float4*)row, v0);           // streaming store: don't pollute L2 (B band lives there)
        __stcs(((float4*)row) + 1, v1);
    }
}

extern "C" void kernel_launch(void* const* d_in, const int* in_sizes, int n_in,
                              void* d_out, int out_size) {
    const float* hidden = (const float*)d_in[0];   // [4*4096, 4096] f32
    const float* qkvw   = (const float*)d_in[1];   // [12288, 4096] f32
    (void)in_sizes; (void)n_in; (void)out_size;    // position_ids unused (identity RoPE)

    float* out = (float*)d_out;                    // q|k|v, each [16384, 4096] f32

    dim3 grid(NT_TILES * MT_TILES);                // 12288 tiles, band-swizzled inside kernel
    dim3 block(THREADS);
    qkv_gemm_kernel<<<grid, block>>>(hidden, qkvw, out);
}

// round 8
// speedup vs baseline: 2.1592x; 2.1592x over previous
#include <cuda_runtime.h>
#include <cstdint>
#include <cstddef>

#define BM 128
#define BN 128
#define BK 16
#define THREADS 256
#define PAD 8                    // stride 136: bank = 8*k+g -> bijection, conflict-free

#define M_DIM 16384
#define N_DIM 12288
#define K_DIM 4096
#define SEG   4096

#define NT_TILES (N_DIM / BN)   // 96
#define MT_TILES (M_DIM / BM)   // 128
#define BAND 48                 // N-tiles per L2 band (96MB of B resident)

static __device__ __forceinline__ uint32_t f2tf32(float x) {
    uint32_t u;
    asm("cvt.rna.tf32.f32 %0, %1;" : "=r"(u) : "f"(x));
    return u;
}

static __device__ __forceinline__ void mma8(float* c, const uint32_t* a, const uint32_t* b) {
    asm volatile(
        "mma.sync.aligned.m16n8k8.row.col.f32.tf32.tf32.f32 "
        "{%0,%1,%2,%3}, {%4,%5,%6,%7}, {%8,%9}, {%0,%1,%2,%3};"
        : "+f"(c[0]), "+f"(c[1]), "+f"(c[2]), "+f"(c[3])
        : "r"(a[0]), "r"(a[1]), "r"(a[2]), "r"(a[3]), "r"(b[0]), "r"(b[1]));
}

__global__ __launch_bounds__(THREADS, 2)
void qkv_tf32_mma_kernel(const float* __restrict__ A,   // [M, K] hidden
                         const float* __restrict__ B,   // [N, K] qkv_proj
                         float* __restrict__ Cout)      // 3 segments of [M, SEG]
{
    // ---- band-swizzled tile coords (B band stays hot in L2) ----
    int tile   = blockIdx.x;
    int band   = tile / (BAND * MT_TILES);
    int within = tile - band * (BAND * MT_TILES);
    int nt     = band * BAND + (within % BAND);
    int mt     = within / BAND;
    const int m0 = mt * BM;
    const int n0 = nt * BN;

    __shared__ uint32_t As[2][BK][BM + PAD];   // tf32 bits, k-major
    __shared__ uint32_t Bs[2][BK][BN + PAD];

    const int tid  = threadIdx.x;
    const int wid  = tid >> 5;
    const int lane = tid & 31;
    const int g    = lane >> 2;      // group id 0..7
    const int t4   = lane & 3;       // thread-in-group 0..3

    // warp tile: 2 (m) x 4 (n) warps, each 64x32
    const int mw = (wid & 1) * 64;
    const int nw = (wid >> 1) * 32;

    // global-load mapping: rows lr, lr+64; float4 at k-offset lc
    const int lr = tid >> 2;
    const int lc = (tid & 3) << 2;
    const float* Aptr = A + (size_t)(m0 + lr) * K_DIM + lc;
    const float* Bptr = B + (size_t)(n0 + lr) * K_DIM + lc;

    float acc[4][4][4];
#pragma unroll
    for (int i = 0; i < 4; i++)
#pragma unroll
        for (int j = 0; j < 4; j++)
#pragma unroll
            for (int q = 0; q < 4; q++) acc[i][j][q] = 0.0f;

    const int KT = K_DIM / BK;       // 256

    // ---- prologue: stage k-tile 0 into buffer 0 ----
    {
        float4 a0 = *(const float4*)(Aptr);
        float4 a1 = *(const float4*)(Aptr + (size_t)64 * K_DIM);
        float4 b0 = *(const float4*)(Bptr);
        float4 b1 = *(const float4*)(Bptr + (size_t)64 * K_DIM);
        As[0][lc + 0][lr] = f2tf32(a0.x); As[0][lc + 1][lr] = f2tf32(a0.y);
        As[0][lc + 2][lr] = f2tf32(a0.z); As[0][lc + 3][lr] = f2tf32(a0.w);
        As[0][lc + 0][lr + 64] = f2tf32(a1.x); As[0][lc + 1][lr + 64] = f2tf32(a1.y);
        As[0][lc + 2][lr + 64] = f2tf32(a1.z); As[0][lc + 3][lr + 64] = f2tf32(a1.w);
        Bs[0][lc + 0][lr] = f2tf32(b0.x); Bs[0][lc + 1][lr] = f2tf32(b0.y);
        Bs[0][lc + 2][lr] = f2tf32(b0.z); Bs[0][lc + 3][lr] = f2tf32(b0.w);
        Bs[0][lc + 0][lr + 64] = f2tf32(b1.x); Bs[0][lc + 1][lr + 64] = f2tf32(b1.y);
        Bs[0][lc + 2][lr + 64] = f2tf32(b1.z); Bs[0][lc + 3][lr + 64] = f2tf32(b1.w);
    }
    __syncthreads();

    int buf = 0;
    for (int kt = 0; kt < KT - 1; kt++) {
        // 1) prefetch next k-tile (LDG latency hidden under 32 mma below)
        const float* ap = Aptr + (size_t)(kt + 1) * BK;
        const float* bp = Bptr + (size_t)(kt + 1) * BK;
        float4 na0 = *(const float4*)(ap);
        float4 na1 = *(const float4*)(ap + (size_t)64 * K_DIM);
        float4 nb0 = *(const float4*)(bp);
        float4 nb1 = *(const float4*)(bp + (size_t)64 * K_DIM);

        // 2) compute: 2 k-steps of 8, 16 mma each
#pragma unroll
        for (int ks = 0; ks < 2; ks++) {
            const int k0 = ks * 8;
            uint32_t a[4][4], b[4][2];
#pragma unroll
            for (int i = 0; i < 4; i++) {
                const int m = mw + i * 16 + g;
                a[i][0] = As[buf][k0 + t4][m];
                a[i][1] = As[buf][k0 + t4][m + 8];
                a[i][2] = As[buf][k0 + t4 + 4][m];
                a[i][3] = As[buf][k0 + t4 + 4][m + 8];
            }
#pragma unroll
            for (int j = 0; j < 4; j++) {
                const int n = nw + j * 8 + g;
                b[j][0] = Bs[buf][k0 + t4][n];
                b[j][1] = Bs[buf][k0 + t4 + 4][n];
            }
#pragma unroll
            for (int i = 0; i < 4; i++)
#pragma unroll
                for (int j = 0; j < 4; j++) mma8(acc[i][j], a[i], b[j]);
        }

        // 3) stage prefetched tile into other buffer
        const int nb = buf ^ 1;
        As[nb][lc + 0][lr] = f2tf32(na0.x); As[nb][lc + 1][lr] = f2tf32(na0.y);
        As[nb][lc + 2][lr] = f2tf32(na0.z); As[nb][lc + 3][lr] = f2tf32(na0.w);
        As[nb][lc + 0][lr + 64] = f2tf32(na1.x); As[nb][lc + 1][lr + 64] = f2tf32(na1.y);
        As[nb][lc + 2][lr + 64] = f2tf32(na1.z); As[nb][lc + 3][lr + 64] = f2tf32(na1.w);
        Bs[nb][lc + 0][lr] = f2tf32(nb0.x); Bs[nb][lc + 1][lr] = f2tf32(nb0.y);
        Bs[nb][lc + 2][lr] = f2tf32(nb0.z); Bs[nb][lc + 3][lr] = f2tf32(nb0.w);
        Bs[nb][lc + 0][lr + 64] = f2tf32(nb1.x); Bs[nb][lc + 1][lr + 64] = f2tf32(nb1.y);
        Bs[nb][lc + 2][lr + 64] = f2tf32(nb1.z); Bs[nb][lc + 3][lr + 64] = f2tf32(nb1.w);

        __syncthreads();
        buf ^= 1;
    }

    // peeled last k-tile
#pragma unroll
    for (int ks = 0; ks < 2; ks++) {
        const int k0 = ks * 8;
        uint32_t a[4][4], b[4][2];
#pragma unroll
        for (int i = 0; i < 4; i++) {
            const int m = mw + i * 16 + g;
            a[i][0] = As[buf][k0 + t4][m];
            a[i][1] = As[buf][k0 + t4][m + 8];
            a[i][2] = As[buf][k0 + t4 + 4][m];
            a[i][3] = As[buf][k0 + t4 + 4][m + 8];
        }
#pragma unroll
        for (int j = 0; j < 4; j++) {
            const int n = nw + j * 8 + g;
            b[j][0] = Bs[buf][k0 + t4][n];
            b[j][1] = Bs[buf][k0 + t4 + 4][n];
        }
#pragma unroll
        for (int i = 0; i < 4; i++)
#pragma unroll
            for (int j = 0; j < 4; j++) mma8(acc[i][j], a[i], b[j]);
    }

    // ---- epilogue: c frag (g,2t4) layout; float2 streaming stores ----
    const int seg = n0 >> 12;
    const int cbase = (n0 & (SEG - 1)) + nw + 2 * t4;
    float* outseg = Cout + (size_t)seg * ((size_t)M_DIM * SEG);

#pragma unroll
    for (int i = 0; i < 4; i++) {
        const int mrow = m0 + mw + i * 16 + g;
        float* r0 = outseg + (size_t)mrow * SEG + cbase;
        float* r1 = outseg + (size_t)(mrow + 8) * SEG + cbase;
#pragma unroll
        for (int j = 0; j < 4; j++) {
            __stcs((float2*)(r0 + j * 8), make_float2(acc[i][j][0], acc[i][j][1]));
            __stcs((float2*)(r1 + j * 8), make_float2(acc[i][j][2], acc[i][j][3]));
        }
    }
}

extern "C" void kernel_launch(void* const* d_in, const int* in_sizes, int n_in,
                              void* d_out, int out_size) {
    const float* hidden = (const float*)d_in[0];   // [16384, 4096] f32
    const float* qkvw   = (const float*)d_in[1];   // [12288, 4096] f32
    (void)in_sizes; (void)n_in; (void)out_size;    // position_ids unused (identity RoPE)
    float* out = (float*)d_out;

    qkv_tf32_mma_kernel<<<NT_TILES * MT_TILES, THREADS>>>(hidden, qkvw, out);
}